// round 7
// baseline (speedup 1.0000x reference)
#include <cuda_runtime.h>

typedef unsigned long long ULL;

// Problem dims (hardcoded per reference)
constexpr int B = 4, L = 4096, H = 16, D = 64, M = 256;
constexpr float SCALE = 0.35355339059327373f;   // 64^-0.25
constexpr float KEPS = 1e-3f;                    // kernel epsilon
constexpr float ZEPS = 1e-6f;                    // Z epsilon

// Global scratch (no allocations allowed)
__device__ __align__(16) float g_KV[B * H * M * D];   // 4 MB
__device__ __align__(16) float g_Ksum[B * H * M];     // 64 KB

// ---------------- f32x2 helpers (sm_103a packed fp32) ----------------
__device__ __forceinline__ void fma2(ULL& d, ULL a, ULL b) {
    asm("fma.rn.f32x2 %0, %1, %2, %0;" : "+l"(d) : "l"(a), "l"(b));
}
__device__ __forceinline__ ULL pack2(float x) {
    ULL r; unsigned int u = __float_as_uint(x);
    asm("mov.b64 %0, {%1, %1};" : "=l"(r) : "r"(u));
    return r;
}
__device__ __forceinline__ void unpack2(ULL p, float& lo, float& hi) {
    unsigned int a, b;
    asm("mov.b64 {%0, %1}, %2;" : "=r"(a), "=r"(b) : "l"(p));
    lo = __uint_as_float(a); hi = __uint_as_float(b);
}

// ---------------- zero scratch ----------------
__global__ void zero_kernel() {
    int i = blockIdx.x * 256 + threadIdx.x;
    float4 z = make_float4(0.f, 0.f, 0.f, 0.f);
    constexpr int NKV4 = (B * H * M * D) / 4;   // 262144
    if (i < NKV4)
        reinterpret_cast<float4*>(g_KV)[i] = z;
    else
        reinterpret_cast<float4*>(g_Ksum)[i - NKV4] = z;
}
constexpr int ZERO_BLOCKS = (B * H * M * D + B * H * M) / 4 / 256;  // 1040

// ---------------- kernel 1: KV = phi(K)^T @ V, Ksum = sum phi(K) ----------------
constexpr int SCHUNK = 512;
constexpr int TS = 16;
constexpr int P_PAD = 66;

// smem layout (float offsets)
constexpr int SM1_P  = 0;                       // 256*66 = 16896
constexpr int SM1_K  = SM1_P + M * P_PAD;       // 16 * 64
constexpr int SM1_V  = SM1_K + TS * 64;         // 16 * 64
constexpr int SM1_KF = SM1_V + TS * 64;         // 16 * 256
constexpr int SM1_FLOATS = SM1_KF + TS * M;     // 23040
constexpr int SM1_BYTES  = SM1_FLOATS * 4;      // 92160

__global__ __launch_bounds__(256, 2)
void k1_kernel(const float* __restrict__ kg, const float* __restrict__ vg,
               const float* __restrict__ Pg) {
    extern __shared__ float sm[];
    float* P_s  = sm + SM1_P;
    float* k_s  = sm + SM1_K;
    float* v_s  = sm + SM1_V;
    float* kf_s = sm + SM1_KF;

    const int t  = threadIdx.x;
    const int b  = blockIdx.z, h = blockIdx.y;
    const int bh = b * H + h;
    const int s0 = blockIdx.x * SCHUNK;

    // Load P (256x64) into padded smem, conflict-free row layout
    #pragma unroll 4
    for (int i = t; i < M * D / 4; i += 256) {
        float4 p4 = reinterpret_cast<const float4*>(Pg)[i];
        int m = i >> 4, d = (i & 15) << 2;
        float* dst = P_s + m * P_PAD + d;
        dst[0] = p4.x; dst[1] = p4.y; dst[2] = p4.z; dst[3] = p4.w;
    }

    // Register KV tile: thread owns 4 consecutive m rows x 16 d cols (as 8 f32x2)
    const int mq = (t & 63) << 2;
    const int dq = (t >> 6) << 4;
    ULL acc[4][8];
    #pragma unroll
    for (int i = 0; i < 4; ++i)
        #pragma unroll
        for (int j = 0; j < 8; ++j) acc[i][j] = 0ull;
    float ksum_acc = 0.f;

    const int r = t >> 4;            // tile row 0..15
    const int c = (t & 15) << 2;     // d offset 0..60

    #pragma unroll 1
    for (int tile = 0; tile < SCHUNK / TS; ++tile) {
        // load k,v tiles (16 rows x 64)
        {
            int s = s0 + tile * TS + r;
            int gidx = ((((b * L + s) * H + h) * D) + c) >> 2;
            float4 k4 = reinterpret_cast<const float4*>(kg)[gidx];
            float4 v4 = reinterpret_cast<const float4*>(vg)[gidx];
            *reinterpret_cast<float4*>(k_s + r * 64 + c) = k4;
            *reinterpret_cast<float4*>(v_s + r * 64 + c) = v4;
        }
        __syncthreads();

        // step 3: Kf[ss][m=t] = relu(scale * k[ss].P[m]) + eps   (f32x2 over d)
        {
            const float* Pr = P_s + t * P_PAD;
            #pragma unroll 1
            for (int half = 0; half < 2; ++half) {
                ULL dacc[8] = {0ull,0ull,0ull,0ull,0ull,0ull,0ull,0ull};
                #pragma unroll 8
                for (int d2 = 0; d2 < 32; ++d2) {
                    ULL p2 = *reinterpret_cast<const ULL*>(Pr + 2 * d2);
                    #pragma unroll
                    for (int ss = 0; ss < 8; ++ss) {
                        ULL k2 = *reinterpret_cast<const ULL*>(k_s + (half * 8 + ss) * 64 + 2 * d2);
                        fma2(dacc[ss], k2, p2);
                    }
                }
                #pragma unroll
                for (int ss = 0; ss < 8; ++ss) {
                    float lo, hi; unpack2(dacc[ss], lo, hi);
                    float kf = fmaxf((lo + hi) * SCALE, 0.f) + KEPS;
                    kf_s[(half * 8 + ss) * M + t] = kf;
                    ksum_acc += kf;
                }
            }
        }
        __syncthreads();

        // step 5: rank-16 outer-product update of KV tile
        #pragma unroll
        for (int ss = 0; ss < TS; ++ss) {
            float4 kf4 = *reinterpret_cast<const float4*>(kf_s + ss * M + mq);
            ULL km0 = pack2(kf4.x), km1 = pack2(kf4.y), km2 = pack2(kf4.z), km3 = pack2(kf4.w);
            const longlong2* vr = reinterpret_cast<const longlong2*>(v_s + ss * 64 + dq);
            #pragma unroll
            for (int j2 = 0; j2 < 4; ++j2) {
                longlong2 vv = vr[j2];
                ULL va = (ULL)vv.x, vb = (ULL)vv.y;
                fma2(acc[0][2 * j2], va, km0); fma2(acc[0][2 * j2 + 1], vb, km0);
                fma2(acc[1][2 * j2], va, km1); fma2(acc[1][2 * j2 + 1], vb, km1);
                fma2(acc[2][2 * j2], va, km2); fma2(acc[2][2 * j2 + 1], vb, km2);
                fma2(acc[3][2 * j2], va, km3); fma2(acc[3][2 * j2 + 1], vb, km3);
            }
        }
        __syncthreads();
    }

    // epilogue: reduce partial KV / Ksum into global scratch
    atomicAdd(&g_Ksum[bh * M + t], ksum_acc);
    #pragma unroll
    for (int i = 0; i < 4; ++i) {
        float* dst = g_KV + (bh * M + mq + i) * D + dq;
        #pragma unroll
        for (int j = 0; j < 8; ++j) {
            float lo, hi; unpack2(acc[i][j], lo, hi);
            atomicAdd(dst + 2 * j,     lo);
            atomicAdd(dst + 2 * j + 1, hi);
        }
    }
}

// ---------------- kernel 2: out = (phi(Q) @ KV) / (phi(Q).Ksum) ----------------
constexpr int LT = 64;            // l-tile
constexpr int QT_PAD = 66;
constexpr int QF_PAD = 257;

constexpr int SM2_P  = 0;                        // 256*66 = 16896
constexpr int SM2_KV = SM2_P + M * P_PAD;        // 16384
constexpr int SM2_QT = SM2_KV + M * D;           // 64*66 = 4224
constexpr int SM2_QF = SM2_QT + LT * QT_PAD;     // 64*257 = 16448
constexpr int SM2_KS = SM2_QF + LT * QF_PAD;     // 256
constexpr int SM2_Z  = SM2_KS + M;               // 64
constexpr int SM2_FLOATS = SM2_Z + LT;           // 54272
constexpr int SM2_BYTES  = SM2_FLOATS * 4;       // 217088

__global__ __launch_bounds__(256, 1)
void k2_kernel(const float* __restrict__ qg, const float* __restrict__ Pg,
               float* __restrict__ outg) {
    extern __shared__ float sm[];
    float* P_s  = sm + SM2_P;
    float* KV_s = sm + SM2_KV;
    float* qT_s = sm + SM2_QT;
    float* qf_s = sm + SM2_QF;
    float* ks_s = sm + SM2_KS;
    float* z_s  = sm + SM2_Z;

    const int t  = threadIdx.x;
    const int b  = blockIdx.z, h = blockIdx.y;
    const int bh = b * H + h;
    const int l0 = blockIdx.x * LT;

    // P into padded smem
    #pragma unroll 4
    for (int i = t; i < M * D / 4; i += 256) {
        float4 p4 = reinterpret_cast<const float4*>(Pg)[i];
        int m = i >> 4, d = (i & 15) << 2;
        float* dst = P_s + m * P_PAD + d;
        dst[0] = p4.x; dst[1] = p4.y; dst[2] = p4.z; dst[3] = p4.w;
    }
    // KV tile (unpadded, 256x64)
    #pragma unroll 4
    for (int i = t; i < M * D / 4; i += 256)
        reinterpret_cast<float4*>(KV_s)[i] =
            reinterpret_cast<const float4*>(g_KV + bh * M * D)[i];
    // Ksum (+eps)
    ks_s[t] = g_Ksum[bh * M + t] + ZEPS;
    // q tile transposed: qT[d][l]
    #pragma unroll 4
    for (int i = t; i < LT * D; i += 256) {
        int l = i >> 6, d = i & 63;
        qT_s[d * QT_PAD + l] = qg[((b * L + l0 + l) * H + h) * D + d];
    }
    __syncthreads();

    // Stage A: Qf[l][m=t] via f32x2 pairs over l
    {
        const float* Pr = P_s + t * P_PAD;
        #pragma unroll 1
        for (int half = 0; half < 2; ++half) {
            ULL a2[16];
            #pragma unroll
            for (int j = 0; j < 16; ++j) a2[j] = 0ull;
            #pragma unroll 8
            for (int d = 0; d < 64; ++d) {
                ULL pd = pack2(Pr[d]);
                const ULL* qr = reinterpret_cast<const ULL*>(qT_s + d * QT_PAD + half * 32);
                #pragma unroll
                for (int j = 0; j < 16; ++j) fma2(a2[j], qr[j], pd);
            }
            #pragma unroll
            for (int j = 0; j < 16; ++j) {
                float lo, hi; unpack2(a2[j], lo, hi);
                int l = half * 32 + 2 * j;
                qf_s[l * QF_PAD + t]       = fmaxf(lo * SCALE, 0.f) + KEPS;
                qf_s[(l + 1) * QF_PAD + t] = fmaxf(hi * SCALE, 0.f) + KEPS;
            }
        }
    }
    __syncthreads();

    // z[l] = 1 / (Qf[l] . Ksum)
    if (t < LT) {
        float zs = 0.f;
        const float* qr = qf_s + t * QF_PAD;
        #pragma unroll 8
        for (int m = 0; m < M; ++m) zs += qr[m] * ks_s[m];
        z_s[t] = 1.0f / zs;
    }
    __syncthreads();

    // Stage B: out[l][d] = (Qf[l] @ KV[:, d]) * z[l]
    {
        const int l  = t >> 2;
        const int dg = (t & 3) << 4;
        ULL acc2[8];
        #pragma unroll
        for (int j = 0; j < 8; ++j) acc2[j] = 0ull;
        const float* qr = qf_s + l * QF_PAD;
        #pragma unroll 4
        for (int m = 0; m < M; ++m) {
            ULL qd = pack2(qr[m]);
            const longlong2* kr = reinterpret_cast<const longlong2*>(KV_s + m * D + dg);
            #pragma unroll
            for (int j2 = 0; j2 < 4; ++j2) {
                longlong2 kk = kr[j2];
                fma2(acc2[2 * j2],     (ULL)kk.x, qd);
                fma2(acc2[2 * j2 + 1], (ULL)kk.y, qd);
            }
        }
        float zi = z_s[l];
        float4* dst = reinterpret_cast<float4*>(outg + ((size_t)(b * L + l0 + l) * H + h) * D + dg);
        #pragma unroll
        for (int j2 = 0; j2 < 4; ++j2) {
            float lo0, hi0, lo1, hi1;
            unpack2(acc2[2 * j2],     lo0, hi0);
            unpack2(acc2[2 * j2 + 1], lo1, hi1);
            dst[j2] = make_float4(lo0 * zi, hi0 * zi, lo1 * zi, hi1 * zi);
        }
    }
}

// ---------------- launch ----------------
extern "C" void kernel_launch(void* const* d_in, const int* in_sizes, int n_in,
                              void* d_out, int out_size) {
    const float* q = (const float*)d_in[0];
    const float* k = (const float*)d_in[1];
    const float* v = (const float*)d_in[2];
    const float* P = (const float*)d_in[3];
    float* out = (float*)d_out;

    cudaFuncSetAttribute(k1_kernel, cudaFuncAttributeMaxDynamicSharedMemorySize, SM1_BYTES);
    cudaFuncSetAttribute(k2_kernel, cudaFuncAttributeMaxDynamicSharedMemorySize, SM2_BYTES);

    zero_kernel<<<ZERO_BLOCKS, 256>>>();
    k1_kernel<<<dim3(L / SCHUNK, H, B), 256, SM1_BYTES>>>(k, v, P);
    k2_kernel<<<dim3(L / LT, H, B), 256, SM2_BYTES>>>(q, P, out);
}

// round 8
// speedup vs baseline: 1.0004x; 1.0004x over previous
#include <cuda_runtime.h>

typedef unsigned long long ULL;

// Problem dims (hardcoded per reference)
constexpr int B = 4, L = 4096, H = 16, D = 64, M = 256;
constexpr float SCALE = 0.35355339059327373f;   // 64^-0.25
constexpr float KEPS = 1e-3f;                    // kernel epsilon
constexpr float ZEPS = 1e-6f;                    // Z epsilon

// Global scratch (no allocations allowed)
__device__ __align__(16) float g_KV[B * H * M * D];   // 4 MB
__device__ __align__(16) float g_Ksum[B * H * M];     // 64 KB

// ---------------- f32x2 helpers (sm_103a packed fp32) ----------------
__device__ __forceinline__ void fma2(ULL& d, ULL a, ULL b) {
    asm("fma.rn.f32x2 %0, %1, %2, %0;" : "+l"(d) : "l"(a), "l"(b));
}
__device__ __forceinline__ ULL pack2(float x) {
    ULL r; unsigned int u = __float_as_uint(x);
    asm("mov.b64 %0, {%1, %1};" : "=l"(r) : "r"(u));
    return r;
}
__device__ __forceinline__ void unpack2(ULL p, float& lo, float& hi) {
    unsigned int a, b;
    asm("mov.b64 {%0, %1}, %2;" : "=r"(a), "=r"(b) : "l"(p));
    lo = __uint_as_float(a); hi = __uint_as_float(b);
}

// ---------------- zero scratch ----------------
__global__ void zero_kernel() {
    int i = blockIdx.x * 256 + threadIdx.x;
    float4 z = make_float4(0.f, 0.f, 0.f, 0.f);
    constexpr int NKV4 = (B * H * M * D) / 4;   // 262144
    if (i < NKV4)
        reinterpret_cast<float4*>(g_KV)[i] = z;
    else
        reinterpret_cast<float4*>(g_Ksum)[i - NKV4] = z;
}
constexpr int ZERO_BLOCKS = (B * H * M * D + B * H * M) / 4 / 256;  // 1040

// ---------------- kernel 1: KV = phi(K)^T @ V, Ksum = sum phi(K) ----------------
constexpr int SCHUNK = 512;
constexpr int TS = 16;
constexpr int P_PAD = 66;

// smem layout (float offsets)
constexpr int SM1_P  = 0;                       // 256*66 = 16896
constexpr int SM1_K  = SM1_P + M * P_PAD;       // 16 * 64
constexpr int SM1_V  = SM1_K + TS * 64;         // 16 * 64
constexpr int SM1_KF = SM1_V + TS * 64;         // 16 * 256
constexpr int SM1_FLOATS = SM1_KF + TS * M;     // 23040
constexpr int SM1_BYTES  = SM1_FLOATS * 4;      // 92160

__global__ __launch_bounds__(256, 2)
void k1_kernel(const float* __restrict__ kg, const float* __restrict__ vg,
               const float* __restrict__ Pg) {
    extern __shared__ float sm[];
    float* P_s  = sm + SM1_P;
    float* k_s  = sm + SM1_K;
    float* v_s  = sm + SM1_V;
    float* kf_s = sm + SM1_KF;

    const int t  = threadIdx.x;
    const int b  = blockIdx.z, h = blockIdx.y;
    const int bh = b * H + h;
    const int s0 = blockIdx.x * SCHUNK;

    // Load P (256x64) into padded smem, conflict-free row layout
    #pragma unroll 4
    for (int i = t; i < M * D / 4; i += 256) {
        float4 p4 = reinterpret_cast<const float4*>(Pg)[i];
        int m = i >> 4, d = (i & 15) << 2;
        float* dst = P_s + m * P_PAD + d;
        dst[0] = p4.x; dst[1] = p4.y; dst[2] = p4.z; dst[3] = p4.w;
    }

    // Register KV tile: thread owns 4 consecutive m rows x 16 d cols (as 8 f32x2)
    const int mq = (t & 63) << 2;
    const int dq = (t >> 6) << 4;
    ULL acc[4][8];
    #pragma unroll
    for (int i = 0; i < 4; ++i)
        #pragma unroll
        for (int j = 0; j < 8; ++j) acc[i][j] = 0ull;
    float ksum_acc = 0.f;

    const int r = t >> 4;            // tile row 0..15
    const int c = (t & 15) << 2;     // d offset 0..60

    #pragma unroll 1
    for (int tile = 0; tile < SCHUNK / TS; ++tile) {
        // load k,v tiles (16 rows x 64)
        {
            int s = s0 + tile * TS + r;
            int gidx = ((((b * L + s) * H + h) * D) + c) >> 2;
            float4 k4 = reinterpret_cast<const float4*>(kg)[gidx];
            float4 v4 = reinterpret_cast<const float4*>(vg)[gidx];
            *reinterpret_cast<float4*>(k_s + r * 64 + c) = k4;
            *reinterpret_cast<float4*>(v_s + r * 64 + c) = v4;
        }
        __syncthreads();

        // step 3: Kf[ss][m=t] = relu(scale * k[ss].P[m]) + eps   (f32x2 over d)
        {
            const float* Pr = P_s + t * P_PAD;
            #pragma unroll 1
            for (int half = 0; half < 2; ++half) {
                ULL dacc[8] = {0ull,0ull,0ull,0ull,0ull,0ull,0ull,0ull};
                #pragma unroll 8
                for (int d2 = 0; d2 < 32; ++d2) {
                    ULL p2 = *reinterpret_cast<const ULL*>(Pr + 2 * d2);
                    #pragma unroll
                    for (int ss = 0; ss < 8; ++ss) {
                        ULL k2 = *reinterpret_cast<const ULL*>(k_s + (half * 8 + ss) * 64 + 2 * d2);
                        fma2(dacc[ss], k2, p2);
                    }
                }
                #pragma unroll
                for (int ss = 0; ss < 8; ++ss) {
                    float lo, hi; unpack2(dacc[ss], lo, hi);
                    float kf = fmaxf((lo + hi) * SCALE, 0.f) + KEPS;
                    kf_s[(half * 8 + ss) * M + t] = kf;
                    ksum_acc += kf;
                }
            }
        }
        __syncthreads();

        // step 5: rank-16 outer-product update of KV tile
        #pragma unroll
        for (int ss = 0; ss < TS; ++ss) {
            float4 kf4 = *reinterpret_cast<const float4*>(kf_s + ss * M + mq);
            ULL km0 = pack2(kf4.x), km1 = pack2(kf4.y), km2 = pack2(kf4.z), km3 = pack2(kf4.w);
            const longlong2* vr = reinterpret_cast<const longlong2*>(v_s + ss * 64 + dq);
            #pragma unroll
            for (int j2 = 0; j2 < 4; ++j2) {
                longlong2 vv = vr[j2];
                ULL va = (ULL)vv.x, vb = (ULL)vv.y;
                fma2(acc[0][2 * j2], va, km0); fma2(acc[0][2 * j2 + 1], vb, km0);
                fma2(acc[1][2 * j2], va, km1); fma2(acc[1][2 * j2 + 1], vb, km1);
                fma2(acc[2][2 * j2], va, km2); fma2(acc[2][2 * j2 + 1], vb, km2);
                fma2(acc[3][2 * j2], va, km3); fma2(acc[3][2 * j2 + 1], vb, km3);
            }
        }
        __syncthreads();
    }

    // epilogue: reduce partial KV / Ksum into global scratch
    atomicAdd(&g_Ksum[bh * M + t], ksum_acc);
    #pragma unroll
    for (int i = 0; i < 4; ++i) {
        float* dst = g_KV + (bh * M + mq + i) * D + dq;
        #pragma unroll
        for (int j = 0; j < 8; ++j) {
            float lo, hi; unpack2(acc[i][j], lo, hi);
            atomicAdd(dst + 2 * j,     lo);
            atomicAdd(dst + 2 * j + 1, hi);
        }
    }
}

// ---------------- kernel 2: out = (phi(Q) @ KV) / (phi(Q).Ksum) ----------------
constexpr int LT = 64;            // l-tile
constexpr int QT_PAD = 66;
constexpr int QF_PAD = 257;

constexpr int SM2_P  = 0;                        // 256*66 = 16896
constexpr int SM2_KV = SM2_P + M * P_PAD;        // 16384
constexpr int SM2_QT = SM2_KV + M * D;           // 64*66 = 4224
constexpr int SM2_QF = SM2_QT + LT * QT_PAD;     // 64*257 = 16448
constexpr int SM2_KS = SM2_QF + LT * QF_PAD;     // 256
constexpr int SM2_Z  = SM2_KS + M;               // 64
constexpr int SM2_FLOATS = SM2_Z + LT;           // 54272
constexpr int SM2_BYTES  = SM2_FLOATS * 4;       // 217088

__global__ __launch_bounds__(256, 1)
void k2_kernel(const float* __restrict__ qg, const float* __restrict__ Pg,
               float* __restrict__ outg) {
    extern __shared__ float sm[];
    float* P_s  = sm + SM2_P;
    float* KV_s = sm + SM2_KV;
    float* qT_s = sm + SM2_QT;
    float* qf_s = sm + SM2_QF;
    float* ks_s = sm + SM2_KS;
    float* z_s  = sm + SM2_Z;

    const int t  = threadIdx.x;
    const int b  = blockIdx.z, h = blockIdx.y;
    const int bh = b * H + h;
    const int l0 = blockIdx.x * LT;

    // P into padded smem
    #pragma unroll 4
    for (int i = t; i < M * D / 4; i += 256) {
        float4 p4 = reinterpret_cast<const float4*>(Pg)[i];
        int m = i >> 4, d = (i & 15) << 2;
        float* dst = P_s + m * P_PAD + d;
        dst[0] = p4.x; dst[1] = p4.y; dst[2] = p4.z; dst[3] = p4.w;
    }
    // KV tile (unpadded, 256x64)
    #pragma unroll 4
    for (int i = t; i < M * D / 4; i += 256)
        reinterpret_cast<float4*>(KV_s)[i] =
            reinterpret_cast<const float4*>(g_KV + bh * M * D)[i];
    // Ksum (+eps)
    ks_s[t] = g_Ksum[bh * M + t] + ZEPS;
    // q tile transposed: qT[d][l]
    #pragma unroll 4
    for (int i = t; i < LT * D; i += 256) {
        int l = i >> 6, d = i & 63;
        qT_s[d * QT_PAD + l] = qg[((b * L + l0 + l) * H + h) * D + d];
    }
    __syncthreads();

    // Stage A: Qf[l][m=t] via f32x2 pairs over l
    {
        const float* Pr = P_s + t * P_PAD;
        #pragma unroll 1
        for (int half = 0; half < 2; ++half) {
            ULL a2[16];
            #pragma unroll
            for (int j = 0; j < 16; ++j) a2[j] = 0ull;
            #pragma unroll 8
            for (int d = 0; d < 64; ++d) {
                ULL pd = pack2(Pr[d]);
                const ULL* qr = reinterpret_cast<const ULL*>(qT_s + d * QT_PAD + half * 32);
                #pragma unroll
                for (int j = 0; j < 16; ++j) fma2(a2[j], qr[j], pd);
            }
            #pragma unroll
            for (int j = 0; j < 16; ++j) {
                float lo, hi; unpack2(a2[j], lo, hi);
                int l = half * 32 + 2 * j;
                qf_s[l * QF_PAD + t]       = fmaxf(lo * SCALE, 0.f) + KEPS;
                qf_s[(l + 1) * QF_PAD + t] = fmaxf(hi * SCALE, 0.f) + KEPS;
            }
        }
    }
    __syncthreads();

    // z[l] = 1 / (Qf[l] . Ksum)
    if (t < LT) {
        float zs = 0.f;
        const float* qr = qf_s + t * QF_PAD;
        #pragma unroll 8
        for (int m = 0; m < M; ++m) zs += qr[m] * ks_s[m];
        z_s[t] = 1.0f / zs;
    }
    __syncthreads();

    // Stage B: out[l][d] = (Qf[l] @ KV[:, d]) * z[l]
    {
        const int l  = t >> 2;
        const int dg = (t & 3) << 4;
        ULL acc2[8];
        #pragma unroll
        for (int j = 0; j < 8; ++j) acc2[j] = 0ull;
        const float* qr = qf_s + l * QF_PAD;
        #pragma unroll 4
        for (int m = 0; m < M; ++m) {
            ULL qd = pack2(qr[m]);
            const longlong2* kr = reinterpret_cast<const longlong2*>(KV_s + m * D + dg);
            #pragma unroll
            for (int j2 = 0; j2 < 4; ++j2) {
                longlong2 kk = kr[j2];
                fma2(acc2[2 * j2],     (ULL)kk.x, qd);
                fma2(acc2[2 * j2 + 1], (ULL)kk.y, qd);
            }
        }
        float zi = z_s[l];
        float4* dst = reinterpret_cast<float4*>(outg + ((size_t)(b * L + l0 + l) * H + h) * D + dg);
        #pragma unroll
        for (int j2 = 0; j2 < 4; ++j2) {
            float lo0, hi0, lo1, hi1;
            unpack2(acc2[2 * j2],     lo0, hi0);
            unpack2(acc2[2 * j2 + 1], lo1, hi1);
            dst[j2] = make_float4(lo0 * zi, hi0 * zi, lo1 * zi, hi1 * zi);
        }
    }
}

// ---------------- launch ----------------
extern "C" void kernel_launch(void* const* d_in, const int* in_sizes, int n_in,
                              void* d_out, int out_size) {
    const float* q = (const float*)d_in[0];
    const float* k = (const float*)d_in[1];
    const float* v = (const float*)d_in[2];
    const float* P = (const float*)d_in[3];
    float* out = (float*)d_out;

    cudaFuncSetAttribute(k1_kernel, cudaFuncAttributeMaxDynamicSharedMemorySize, SM1_BYTES);
    cudaFuncSetAttribute(k2_kernel, cudaFuncAttributeMaxDynamicSharedMemorySize, SM2_BYTES);

    zero_kernel<<<ZERO_BLOCKS, 256>>>();
    k1_kernel<<<dim3(L / SCHUNK, H, B), 256, SM1_BYTES>>>(k, v, P);
    k2_kernel<<<dim3(L / LT, H, B), 256, SM2_BYTES>>>(q, P, out);
}

// round 9
// speedup vs baseline: 1.0020x; 1.0016x over previous
#include <cuda_runtime.h>

typedef unsigned long long ULL;

// Problem dims (hardcoded per reference)
constexpr int B = 4, L = 4096, H = 16, D = 64, M = 256;
constexpr float SCALE = 0.35355339059327373f;   // 64^-0.25
constexpr float KEPS = 1e-3f;                    // kernel epsilon
constexpr float ZEPS = 1e-6f;                    // Z epsilon

// Global scratch (no allocations allowed)
__device__ __align__(16) float g_KV[B * H * M * D];   // 4 MB
__device__ __align__(16) float g_Ksum[B * H * M];     // 64 KB

// ---------------- f32x2 helpers (sm_103a packed fp32) ----------------
__device__ __forceinline__ void fma2(ULL& d, ULL a, ULL b) {
    asm("fma.rn.f32x2 %0, %1, %2, %0;" : "+l"(d) : "l"(a), "l"(b));
}
__device__ __forceinline__ ULL pack2(float x) {
    ULL r; unsigned int u = __float_as_uint(x);
    asm("mov.b64 %0, {%1, %1};" : "=l"(r) : "r"(u));
    return r;
}
__device__ __forceinline__ void unpack2(ULL p, float& lo, float& hi) {
    unsigned int a, b;
    asm("mov.b64 {%0, %1}, %2;" : "=r"(a), "=r"(b) : "l"(p));
    lo = __uint_as_float(a); hi = __uint_as_float(b);
}

// ---------------- zero scratch ----------------
__global__ void zero_kernel() {
    int i = blockIdx.x * 256 + threadIdx.x;
    float4 z = make_float4(0.f, 0.f, 0.f, 0.f);
    constexpr int NKV4 = (B * H * M * D) / 4;   // 262144
    if (i < NKV4)
        reinterpret_cast<float4*>(g_KV)[i] = z;
    else
        reinterpret_cast<float4*>(g_Ksum)[i - NKV4] = z;
}
constexpr int ZERO_BLOCKS = (B * H * M * D + B * H * M) / 4 / 256;  // 1040

// ---------------- kernel 1: KV = phi(K)^T @ V, Ksum = sum phi(K) ----------------
constexpr int SCHUNK = 512;
constexpr int TS = 16;
constexpr int P_PAD = 66;

// smem layout (float offsets)
constexpr int SM1_P  = 0;                       // 256*66 = 16896
constexpr int SM1_K  = SM1_P + M * P_PAD;       // 16 * 64
constexpr int SM1_V  = SM1_K + TS * 64;         // 16 * 64
constexpr int SM1_KF = SM1_V + TS * 64;         // 16 * 256
constexpr int SM1_FLOATS = SM1_KF + TS * M;     // 23040
constexpr int SM1_BYTES  = SM1_FLOATS * 4;      // 92160

__global__ __launch_bounds__(256, 2)
void k1_kernel(const float* __restrict__ kg, const float* __restrict__ vg,
               const float* __restrict__ Pg) {
    extern __shared__ float sm[];
    float* P_s  = sm + SM1_P;
    float* k_s  = sm + SM1_K;
    float* v_s  = sm + SM1_V;
    float* kf_s = sm + SM1_KF;

    const int t  = threadIdx.x;
    const int b  = blockIdx.z, h = blockIdx.y;
    const int bh = b * H + h;
    const int s0 = blockIdx.x * SCHUNK;

    // Load P (256x64) into padded smem, conflict-free row layout
    #pragma unroll 4
    for (int i = t; i < M * D / 4; i += 256) {
        float4 p4 = reinterpret_cast<const float4*>(Pg)[i];
        int m = i >> 4, d = (i & 15) << 2;
        float* dst = P_s + m * P_PAD + d;
        dst[0] = p4.x; dst[1] = p4.y; dst[2] = p4.z; dst[3] = p4.w;
    }

    // Register KV tile: thread owns 4 consecutive m rows x 16 d cols (as 8 f32x2)
    const int mq = (t & 63) << 2;
    const int dq = (t >> 6) << 4;
    ULL acc[4][8];
    #pragma unroll
    for (int i = 0; i < 4; ++i)
        #pragma unroll
        for (int j = 0; j < 8; ++j) acc[i][j] = 0ull;
    float ksum_acc = 0.f;

    const int r = t >> 4;            // tile row 0..15
    const int c = (t & 15) << 2;     // d offset 0..60

    #pragma unroll 1
    for (int tile = 0; tile < SCHUNK / TS; ++tile) {
        // load k,v tiles (16 rows x 64)
        {
            int s = s0 + tile * TS + r;
            int gidx = ((((b * L + s) * H + h) * D) + c) >> 2;
            float4 k4 = reinterpret_cast<const float4*>(kg)[gidx];
            float4 v4 = reinterpret_cast<const float4*>(vg)[gidx];
            *reinterpret_cast<float4*>(k_s + r * 64 + c) = k4;
            *reinterpret_cast<float4*>(v_s + r * 64 + c) = v4;
        }
        __syncthreads();

        // step 3: Kf[ss][m=t] = relu(scale * k[ss].P[m]) + eps   (f32x2 over d)
        {
            const float* Pr = P_s + t * P_PAD;
            #pragma unroll 1
            for (int half = 0; half < 2; ++half) {
                ULL dacc[8] = {0ull,0ull,0ull,0ull,0ull,0ull,0ull,0ull};
                #pragma unroll 8
                for (int d2 = 0; d2 < 32; ++d2) {
                    ULL p2 = *reinterpret_cast<const ULL*>(Pr + 2 * d2);
                    #pragma unroll
                    for (int ss = 0; ss < 8; ++ss) {
                        ULL k2 = *reinterpret_cast<const ULL*>(k_s + (half * 8 + ss) * 64 + 2 * d2);
                        fma2(dacc[ss], k2, p2);
                    }
                }
                #pragma unroll
                for (int ss = 0; ss < 8; ++ss) {
                    float lo, hi; unpack2(dacc[ss], lo, hi);
                    float kf = fmaxf((lo + hi) * SCALE, 0.f) + KEPS;
                    kf_s[(half * 8 + ss) * M + t] = kf;
                    ksum_acc += kf;
                }
            }
        }
        __syncthreads();

        // step 5: rank-16 outer-product update of KV tile
        #pragma unroll
        for (int ss = 0; ss < TS; ++ss) {
            float4 kf4 = *reinterpret_cast<const float4*>(kf_s + ss * M + mq);
            ULL km0 = pack2(kf4.x), km1 = pack2(kf4.y), km2 = pack2(kf4.z), km3 = pack2(kf4.w);
            const longlong2* vr = reinterpret_cast<const longlong2*>(v_s + ss * 64 + dq);
            #pragma unroll
            for (int j2 = 0; j2 < 4; ++j2) {
                longlong2 vv = vr[j2];
                ULL va = (ULL)vv.x, vb = (ULL)vv.y;
                fma2(acc[0][2 * j2], va, km0); fma2(acc[0][2 * j2 + 1], vb, km0);
                fma2(acc[1][2 * j2], va, km1); fma2(acc[1][2 * j2 + 1], vb, km1);
                fma2(acc[2][2 * j2], va, km2); fma2(acc[2][2 * j2 + 1], vb, km2);
                fma2(acc[3][2 * j2], va, km3); fma2(acc[3][2 * j2 + 1], vb, km3);
            }
        }
        __syncthreads();
    }

    // epilogue: reduce partial KV / Ksum into global scratch
    atomicAdd(&g_Ksum[bh * M + t], ksum_acc);
    #pragma unroll
    for (int i = 0; i < 4; ++i) {
        float* dst = g_KV + (bh * M + mq + i) * D + dq;
        #pragma unroll
        for (int j = 0; j < 8; ++j) {
            float lo, hi; unpack2(acc[i][j], lo, hi);
            atomicAdd(dst + 2 * j,     lo);
            atomicAdd(dst + 2 * j + 1, hi);
        }
    }
}

// ---------------- kernel 2: out = (phi(Q) @ KV) / (phi(Q).Ksum) ----------------
constexpr int LT = 64;            // l-tile
constexpr int QT_PAD = 66;
constexpr int QF_PAD = 257;

constexpr int SM2_P  = 0;                        // 256*66 = 16896
constexpr int SM2_KV = SM2_P + M * P_PAD;        // 16384
constexpr int SM2_QT = SM2_KV + M * D;           // 64*66 = 4224
constexpr int SM2_QF = SM2_QT + LT * QT_PAD;     // 64*257 = 16448
constexpr int SM2_KS = SM2_QF + LT * QF_PAD;     // 256
constexpr int SM2_Z  = SM2_KS + M;               // 64
constexpr int SM2_FLOATS = SM2_Z + LT;           // 54272
constexpr int SM2_BYTES  = SM2_FLOATS * 4;       // 217088

__global__ __launch_bounds__(256, 1)
void k2_kernel(const float* __restrict__ qg, const float* __restrict__ Pg,
               float* __restrict__ outg) {
    extern __shared__ float sm[];
    float* P_s  = sm + SM2_P;
    float* KV_s = sm + SM2_KV;
    float* qT_s = sm + SM2_QT;
    float* qf_s = sm + SM2_QF;
    float* ks_s = sm + SM2_KS;
    float* z_s  = sm + SM2_Z;

    const int t  = threadIdx.x;
    const int b  = blockIdx.z, h = blockIdx.y;
    const int bh = b * H + h;
    const int l0 = blockIdx.x * LT;

    // P into padded smem
    #pragma unroll 4
    for (int i = t; i < M * D / 4; i += 256) {
        float4 p4 = reinterpret_cast<const float4*>(Pg)[i];
        int m = i >> 4, d = (i & 15) << 2;
        float* dst = P_s + m * P_PAD + d;
        dst[0] = p4.x; dst[1] = p4.y; dst[2] = p4.z; dst[3] = p4.w;
    }
    // KV tile (unpadded, 256x64)
    #pragma unroll 4
    for (int i = t; i < M * D / 4; i += 256)
        reinterpret_cast<float4*>(KV_s)[i] =
            reinterpret_cast<const float4*>(g_KV + bh * M * D)[i];
    // Ksum (+eps)
    ks_s[t] = g_Ksum[bh * M + t] + ZEPS;
    // q tile transposed: qT[d][l]
    #pragma unroll 4
    for (int i = t; i < LT * D; i += 256) {
        int l = i >> 6, d = i & 63;
        qT_s[d * QT_PAD + l] = qg[((b * L + l0 + l) * H + h) * D + d];
    }
    __syncthreads();

    // Stage A: Qf[l][m=t] via f32x2 pairs over l
    {
        const float* Pr = P_s + t * P_PAD;
        #pragma unroll 1
        for (int half = 0; half < 2; ++half) {
            ULL a2[16];
            #pragma unroll
            for (int j = 0; j < 16; ++j) a2[j] = 0ull;
            #pragma unroll 8
            for (int d = 0; d < 64; ++d) {
                ULL pd = pack2(Pr[d]);
                const ULL* qr = reinterpret_cast<const ULL*>(qT_s + d * QT_PAD + half * 32);
                #pragma unroll
                for (int j = 0; j < 16; ++j) fma2(a2[j], qr[j], pd);
            }
            #pragma unroll
            for (int j = 0; j < 16; ++j) {
                float lo, hi; unpack2(a2[j], lo, hi);
                int l = half * 32 + 2 * j;
                qf_s[l * QF_PAD + t]       = fmaxf(lo * SCALE, 0.f) + KEPS;
                qf_s[(l + 1) * QF_PAD + t] = fmaxf(hi * SCALE, 0.f) + KEPS;
            }
        }
    }
    __syncthreads();

    // z[l] = 1 / (Qf[l] . Ksum)
    if (t < LT) {
        float zs = 0.f;
        const float* qr = qf_s + t * QF_PAD;
        #pragma unroll 8
        for (int m = 0; m < M; ++m) zs += qr[m] * ks_s[m];
        z_s[t] = 1.0f / zs;
    }
    __syncthreads();

    // Stage B: out[l][d] = (Qf[l] @ KV[:, d]) * z[l]
    {
        const int l  = t >> 2;
        const int dg = (t & 3) << 4;
        ULL acc2[8];
        #pragma unroll
        for (int j = 0; j < 8; ++j) acc2[j] = 0ull;
        const float* qr = qf_s + l * QF_PAD;
        #pragma unroll 4
        for (int m = 0; m < M; ++m) {
            ULL qd = pack2(qr[m]);
            const longlong2* kr = reinterpret_cast<const longlong2*>(KV_s + m * D + dg);
            #pragma unroll
            for (int j2 = 0; j2 < 4; ++j2) {
                longlong2 kk = kr[j2];
                fma2(acc2[2 * j2],     (ULL)kk.x, qd);
                fma2(acc2[2 * j2 + 1], (ULL)kk.y, qd);
            }
        }
        float zi = z_s[l];
        float4* dst = reinterpret_cast<float4*>(outg + ((size_t)(b * L + l0 + l) * H + h) * D + dg);
        #pragma unroll
        for (int j2 = 0; j2 < 4; ++j2) {
            float lo0, hi0, lo1, hi1;
            unpack2(acc2[2 * j2],     lo0, hi0);
            unpack2(acc2[2 * j2 + 1], lo1, hi1);
            dst[j2] = make_float4(lo0 * zi, hi0 * zi, lo1 * zi, hi1 * zi);
        }
    }
}

// ---------------- launch ----------------
extern "C" void kernel_launch(void* const* d_in, const int* in_sizes, int n_in,
                              void* d_out, int out_size) {
    const float* q = (const float*)d_in[0];
    const float* k = (const float*)d_in[1];
    const float* v = (const float*)d_in[2];
    const float* P = (const float*)d_in[3];
    float* out = (float*)d_out;

    cudaFuncSetAttribute(k1_kernel, cudaFuncAttributeMaxDynamicSharedMemorySize, SM1_BYTES);
    cudaFuncSetAttribute(k2_kernel, cudaFuncAttributeMaxDynamicSharedMemorySize, SM2_BYTES);

    zero_kernel<<<ZERO_BLOCKS, 256>>>();
    k1_kernel<<<dim3(L / SCHUNK, H, B), 256, SM1_BYTES>>>(k, v, P);
    k2_kernel<<<dim3(L / LT, H, B), 256, SM2_BYTES>>>(q, P, out);
}